// round 16
// baseline (speedup 1.0000x reference)
#include <cuda_runtime.h>
#include <cstdint>

// 2x trilinear upsample (TF1 legacy, scale=0.5): (4,32,32,32,32) f32 -> (4,64,64,64,32).
//
// FINAL (lock-in) variant. Block = (b, d0, h0), 128 threads; thread (j 0..15,
// cg 0..7) handles two w-cells (12 corner loads, register reuse, 25% fewer
// LDG than naive). The 4 output rows form two 16 KB contiguous spans (D0, D1).
// The D0 span is staged and its TMA store issued BEFORE the D1 span is staged,
// so the write stream starts draining early.
//
// Empirically-settled facts driving this design (6 structural variants, all
// 24.5-24.7 us): the steady-state loop is bound by the compulsory 128 MB
// output write stream at ~5.3 TB/s. Input must be pinned (evict_last 1.0:
// 16 MB stays L2-resident across graph replays, -16 MB DRAM reads/replay);
// output must stream (evict_first) - both output-pinning schemes regressed.

__device__ __forceinline__ float4 f4add(float4 a, float4 b) {
    return make_float4(a.x + b.x, a.y + b.y, a.z + b.z, a.w + b.w);
}
__device__ __forceinline__ float4 f4scale(float4 a, float s) {
    return make_float4(a.x * s, a.y * s, a.z * s, a.w * s);
}
__device__ __forceinline__ uint32_t smem_u32(const void* p) {
    uint32_t a;
    asm("{ .reg .u64 t; cvta.to.shared.u64 t, %1; cvt.u32.u64 %0, t; }"
        : "=r"(a) : "l"(p));
    return a;
}
__device__ __forceinline__ float4 ldg_el(const float4* p, uint64_t pol) {
    float4 v;
    asm volatile("ld.global.nc.L2::cache_hint.v4.f32 {%0,%1,%2,%3}, [%4], %5;"
                 : "=f"(v.x), "=f"(v.y), "=f"(v.z), "=f"(v.w)
                 : "l"(p), "l"(pol));
    return v;
}

__global__ __launch_bounds__(128)
void resize3d_up2_final_kernel(const float4* __restrict__ in, float4* __restrict__ out) {
    // [0..1023] = D0 span (rows H0,H1), [1024..2047] = D1 span
    __shared__ __align__(1024) float4 sbuf[2048];   // 32 KB static

    const int tid = threadIdx.x;
    const int cg  = tid & 7;        // float4 group within C=32
    const int j   = tid >> 3;       // 0..15 -> cells w=2j, 2j+1

    const int blk = blockIdx.x;     // 4096 blocks
    const int h0  = blk & 31;
    const int d0  = (blk >> 5) & 31;
    const int b   = blk >> 10;

    const int wa = 2 * j;
    const int wb = 2 * j + 1;
    const int wc = min(2 * j + 2, 31);
    const int h1 = min(h0 + 1, 31);
    const int d1 = min(d0 + 1, 31);

    uint64_t pol_keep;
    asm volatile("createpolicy.fractional.L2::evict_last.b64 %0, 1.0;"
                 : "=l"(pol_keep));

    // input float4 strides: cg=1, w=8, h=256, d=8192, b=262144
    const float4* __restrict__ ib = in + ((size_t)b << 18) + (size_t)cg;
    const size_t od0 = (size_t)d0 << 13, od1 = (size_t)d1 << 13;
    const size_t oh0 = (size_t)h0 << 8,  oh1 = (size_t)h1 << 8;
    const size_t owa = (size_t)wa << 3, owb = (size_t)wb << 3, owc = (size_t)wc << 3;

    // 4 input rows x 3 w positions
    const float4 A0a = ldg_el(ib + od0 + oh0 + owa, pol_keep);  // (d0,h0)
    const float4 A0b = ldg_el(ib + od0 + oh0 + owb, pol_keep);
    const float4 A0c = ldg_el(ib + od0 + oh0 + owc, pol_keep);
    const float4 A1a = ldg_el(ib + od0 + oh1 + owa, pol_keep);  // (d0,h1)
    const float4 A1b = ldg_el(ib + od0 + oh1 + owb, pol_keep);
    const float4 A1c = ldg_el(ib + od0 + oh1 + owc, pol_keep);
    const float4 B0a = ldg_el(ib + od1 + oh0 + owa, pol_keep);  // (d1,h0)
    const float4 B0b = ldg_el(ib + od1 + oh0 + owb, pol_keep);
    const float4 B0c = ldg_el(ib + od1 + oh0 + owc, pol_keep);
    const float4 B1a = ldg_el(ib + od1 + oh1 + owa, pol_keep);  // (d1,h1)
    const float4 B1b = ldg_el(ib + od1 + oh1 + owb, pol_keep);
    const float4 B1c = ldg_el(ib + od1 + oh1 + owc, pol_keep);

    // h-pair partial sums (needed for D0 span)
    const float4 ha = f4add(A0a, A1a), hb = f4add(A0b, A1b), hc = f4add(A0c, A1c);

    // each thread owns output W = 4j..4j+3 -> smem base 32j + cg per row
    const int e = (j << 5) + cg;

    // ---- stage D0 span: row (D0,H0) = w-lerp of A0, row (D0,H1) = h-lerp ----
    sbuf[e]           = A0a;
    sbuf[e + 8]       = f4scale(f4add(A0a, A0b), 0.5f);
    sbuf[e + 16]      = A0b;
    sbuf[e + 24]      = f4scale(f4add(A0b, A0c), 0.5f);
    sbuf[512 + e]      = f4scale(ha, 0.5f);
    sbuf[512 + e + 8]  = f4scale(f4add(ha, hb), 0.25f);
    sbuf[512 + e + 16] = f4scale(hb, 0.5f);
    sbuf[512 + e + 24] = f4scale(f4add(hb, hc), 0.25f);

    asm volatile("fence.proxy.async.shared::cta;" ::: "memory");
    __syncthreads();

    // output row offset: ((b*64 + D)*64 + H) * 8192 bytes
    char* g0 = (char*)out + (size_t)(((b * 64 + 2 * d0) * 64) + 2 * h0) * 8192;
    char* g1 = g0 + (size_t)64 * 8192;   // D+1

    uint64_t pol_first;
    asm volatile("createpolicy.fractional.L2::evict_first.b64 %0, 1.0;"
                 : "=l"(pol_first));

    if (tid == 0) {
        // D0 span drains while the D1 span is being staged below
        asm volatile("cp.async.bulk.global.shared::cta.bulk_group.L2::cache_hint"
                     " [%0], [%1], %2, %3;"
                     :: "l"(g0), "r"(smem_u32(sbuf)), "r"(16384u), "l"(pol_first)
                     : "memory");
        asm volatile("cp.async.bulk.commit_group;" ::: "memory");
    }

    // ---- stage D1 span: row (D1,H0) = d-lerp, row (D1,H1) = full trilinear ----
    const float4 da = f4add(A0a, B0a), db = f4add(A0b, B0b), dc = f4add(A0c, B0c);
    const float4 qa = f4add(ha, f4add(B0a, B1a));
    const float4 qb = f4add(hb, f4add(B0b, B1b));
    const float4 qc = f4add(hc, f4add(B0c, B1c));

    sbuf[1024 + e]      = f4scale(da, 0.5f);
    sbuf[1024 + e + 8]  = f4scale(f4add(da, db), 0.25f);
    sbuf[1024 + e + 16] = f4scale(db, 0.5f);
    sbuf[1024 + e + 24] = f4scale(f4add(db, dc), 0.25f);
    sbuf[1536 + e]      = f4scale(qa, 0.25f);
    sbuf[1536 + e + 8]  = f4scale(f4add(qa, qb), 0.125f);
    sbuf[1536 + e + 16] = f4scale(qb, 0.25f);
    sbuf[1536 + e + 24] = f4scale(f4add(qb, qc), 0.125f);

    asm volatile("fence.proxy.async.shared::cta;" ::: "memory");
    __syncthreads();

    if (tid == 0) {
        asm volatile("cp.async.bulk.global.shared::cta.bulk_group.L2::cache_hint"
                     " [%0], [%1], %2, %3;"
                     :: "l"(g1), "r"(smem_u32(sbuf + 1024)), "r"(16384u), "l"(pol_first)
                     : "memory");
        asm volatile("cp.async.bulk.commit_group;" ::: "memory");
        // keep the CTA (and its smem) alive until both TMA reads complete
        asm volatile("cp.async.bulk.wait_group 0;" ::: "memory");
    }
    __syncthreads();
}

extern "C" void kernel_launch(void* const* d_in, const int* in_sizes, int n_in,
                              void* d_out, int out_size) {
    (void)in_sizes; (void)n_in; (void)out_size;
    const float4* in = (const float4*)d_in[0];
    float4* out = (float4*)d_out;
    resize3d_up2_final_kernel<<<4096, 128>>>(in, out);
}

// round 17
// speedup vs baseline: 1.0013x; 1.0013x over previous
#include <cuda_runtime.h>
#include <cstdint>

// 2x trilinear upsample (TF1 legacy, scale=0.5): (4,32,32,32,32) f32 -> (4,64,64,64,32).
//
// FINAL kernel (best measured: 24.51 us wall). Block = (b, d0, h0), 128
// threads. Each thread (j 0..15, cg 0..7) handles TWO w-cells (w=2j, 2j+1),
// loading w in {2j, 2j+1, 2j+2} x 4 input rows = 12 float4s (25% fewer LDG
// than one-cell-per-thread; shared corner column reused in registers).
// Outputs (4 rows x 4 float4/thread) staged in 32 KB smem, then two
// contiguous 16 KB TMA bulk stores.
//
// Empirically settled across 7 structural variants (all 24.5-24.7 us):
// the steady-state graph-replay loop is bound by the compulsory 128 MB
// output write stream draining at ~5.2 TB/s. Policies that matter:
//  - input loads evict_last 1.0: the 16 MB input stays L2-resident across
//    replays (removes ~16 MB DRAM reads/replay; worth ~4 us wall).
//  - output stores evict_first: the write stream must drain freely; both
//    output-pinning schemes (fractional 0.7, deterministic batch-split)
//    regressed 4+ us.

__device__ __forceinline__ float4 f4add(float4 a, float4 b) {
    return make_float4(a.x + b.x, a.y + b.y, a.z + b.z, a.w + b.w);
}
__device__ __forceinline__ float4 f4scale(float4 a, float s) {
    return make_float4(a.x * s, a.y * s, a.z * s, a.w * s);
}
__device__ __forceinline__ uint32_t smem_u32(const void* p) {
    uint32_t a;
    asm("{ .reg .u64 t; cvta.to.shared.u64 t, %1; cvt.u32.u64 %0, t; }"
        : "=r"(a) : "l"(p));
    return a;
}
__device__ __forceinline__ float4 ldg_el(const float4* p, uint64_t pol) {
    float4 v;
    asm volatile("ld.global.nc.L2::cache_hint.v4.f32 {%0,%1,%2,%3}, [%4], %5;"
                 : "=f"(v.x), "=f"(v.y), "=f"(v.z), "=f"(v.w)
                 : "l"(p), "l"(pol));
    return v;
}

__global__ __launch_bounds__(128)
void resize3d_up2_wmerge_kernel(const float4* __restrict__ in, float4* __restrict__ out) {
    // 4 output rows of 8 KB each: [D0H0 | D0H1 | D1H0 | D1H1]
    __shared__ __align__(1024) float4 sbuf[2048];   // 32 KB

    const int tid = threadIdx.x;
    const int cg  = tid & 7;        // float4 group within C=32
    const int j   = tid >> 3;       // 0..15 -> cells w=2j, 2j+1

    const int blk = blockIdx.x;     // 4096 blocks
    const int h0  = blk & 31;
    const int d0  = (blk >> 5) & 31;
    const int b   = blk >> 10;

    const int wa = 2 * j;
    const int wb = 2 * j + 1;
    const int wc = min(2 * j + 2, 31);
    const int h1 = min(h0 + 1, 31);
    const int d1 = min(d0 + 1, 31);

    uint64_t pol_keep;
    asm volatile("createpolicy.fractional.L2::evict_last.b64 %0, 1.0;"
                 : "=l"(pol_keep));

    // input float4 strides: cg=1, w=8, h=256, d=8192, b=262144
    const float4* __restrict__ ib = in + ((size_t)b << 18) + (size_t)cg;
    const size_t od0 = (size_t)d0 << 13, od1 = (size_t)d1 << 13;
    const size_t oh0 = (size_t)h0 << 8,  oh1 = (size_t)h1 << 8;
    const size_t owa = (size_t)wa << 3, owb = (size_t)wb << 3, owc = (size_t)wc << 3;

    // 4 input rows x 3 w positions
    const float4 A0a = ldg_el(ib + od0 + oh0 + owa, pol_keep);  // (d0,h0)
    const float4 A0b = ldg_el(ib + od0 + oh0 + owb, pol_keep);
    const float4 A0c = ldg_el(ib + od0 + oh0 + owc, pol_keep);
    const float4 A1a = ldg_el(ib + od0 + oh1 + owa, pol_keep);  // (d0,h1)
    const float4 A1b = ldg_el(ib + od0 + oh1 + owb, pol_keep);
    const float4 A1c = ldg_el(ib + od0 + oh1 + owc, pol_keep);
    const float4 B0a = ldg_el(ib + od1 + oh0 + owa, pol_keep);  // (d1,h0)
    const float4 B0b = ldg_el(ib + od1 + oh0 + owb, pol_keep);
    const float4 B0c = ldg_el(ib + od1 + oh0 + owc, pol_keep);
    const float4 B1a = ldg_el(ib + od1 + oh1 + owa, pol_keep);  // (d1,h1)
    const float4 B1b = ldg_el(ib + od1 + oh1 + owb, pol_keep);
    const float4 B1c = ldg_el(ib + od1 + oh1 + owc, pol_keep);

    // partial sums per w position
    const float4 ha = f4add(A0a, A1a), hb = f4add(A0b, A1b), hc = f4add(A0c, A1c); // h-pairs @d0
    const float4 da = f4add(A0a, B0a), db = f4add(A0b, B0b), dc = f4add(A0c, B0c); // d-pairs @h0
    const float4 qa = f4add(ha, f4add(B0a, B1a));   // all-4 sums
    const float4 qb = f4add(hb, f4add(B0b, B1b));
    const float4 qc = f4add(hc, f4add(B0c, B1c));

    // each thread owns output W = 4j .. 4j+3  -> smem base 32j + cg
    const int e = (j << 5) + cg;
    // row D0,H0
    sbuf[e]           = A0a;
    sbuf[e + 8]       = f4scale(f4add(A0a, A0b), 0.5f);
    sbuf[e + 16]      = A0b;
    sbuf[e + 24]      = f4scale(f4add(A0b, A0c), 0.5f);
    // row D0,H1
    sbuf[512 + e]      = f4scale(ha, 0.5f);
    sbuf[512 + e + 8]  = f4scale(f4add(ha, hb), 0.25f);
    sbuf[512 + e + 16] = f4scale(hb, 0.5f);
    sbuf[512 + e + 24] = f4scale(f4add(hb, hc), 0.25f);
    // row D1,H0
    sbuf[1024 + e]      = f4scale(da, 0.5f);
    sbuf[1024 + e + 8]  = f4scale(f4add(da, db), 0.25f);
    sbuf[1024 + e + 16] = f4scale(db, 0.5f);
    sbuf[1024 + e + 24] = f4scale(f4add(db, dc), 0.25f);
    // row D1,H1
    sbuf[1536 + e]      = f4scale(qa, 0.25f);
    sbuf[1536 + e + 8]  = f4scale(f4add(qa, qb), 0.125f);
    sbuf[1536 + e + 16] = f4scale(qb, 0.25f);
    sbuf[1536 + e + 24] = f4scale(f4add(qb, qc), 0.125f);

    // make generic-proxy smem writes visible to the async (TMA) proxy
    asm volatile("fence.proxy.async.shared::cta;" ::: "memory");
    __syncthreads();

    if (tid == 0) {
        uint64_t pol_first;
        asm volatile("createpolicy.fractional.L2::evict_first.b64 %0, 1.0;"
                     : "=l"(pol_first));
        const uint32_t s0 = smem_u32(sbuf);
        // output row offset: ((b*64 + D)*64 + H) * 8192 bytes
        char* g0 = (char*)out + (size_t)(((b * 64 + 2 * d0) * 64) + 2 * h0) * 8192;
        char* g1 = g0 + (size_t)64 * 8192;   // D+1
        const uint32_t half = 16384u;
        asm volatile("cp.async.bulk.global.shared::cta.bulk_group.L2::cache_hint"
                     " [%0], [%1], %2, %3;"
                     :: "l"(g0), "r"(s0), "r"(half), "l"(pol_first) : "memory");
        asm volatile("cp.async.bulk.global.shared::cta.bulk_group.L2::cache_hint"
                     " [%0], [%1], %2, %3;"
                     :: "l"(g1), "r"(s0 + half), "r"(half), "l"(pol_first) : "memory");
        asm volatile("cp.async.bulk.commit_group;" ::: "memory");
        // keep the CTA (and its smem) alive until the TMA reads complete
        asm volatile("cp.async.bulk.wait_group 0;" ::: "memory");
    }
    __syncthreads();
}

extern "C" void kernel_launch(void* const* d_in, const int* in_sizes, int n_in,
                              void* d_out, int out_size) {
    (void)in_sizes; (void)n_in; (void)out_size;
    const float4* in = (const float4*)d_in[0];
    float4* out = (float4*)d_out;
    resize3d_up2_wmerge_kernel<<<4096, 128>>>(in, out);
}